// round 1
// baseline (speedup 1.0000x reference)
#include <cuda_runtime.h>
#include <math.h>

// ---------------- problem constants ----------------
#define NTOT   22743      // 1083 + 4332 + 17328
#define N0     1083
#define N1     4332
#define N2     17328
#define OFF1   1083
#define OFF2   5415
#define BATCH  8
#define TOPK   1000
#define NCAND  3000       // 3 levels * 1000
#define MAXDET 100
#define IMGMAX 607

// ---------------- device scratch (no allocation allowed) ----------------
__device__ float g_score[BATCH * NTOT];
__device__ int4  g_box[BATCH * NTOT];
__device__ int   g_cls[BATCH * NTOT];

__device__ float g_cscore[BATCH * NCAND];
__device__ int4  g_cbox[BATCH * NCAND];
__device__ int   g_ccls[BATCH * NCAND];

__device__ __forceinline__ float sigm(float x) { return 1.0f / (1.0f + expf(-x)); }

// ---------------- stage 1: decode all anchors ----------------
__global__ void decode_kernel(
    const float* __restrict__ obj0, const float* __restrict__ reg0,
    const float* __restrict__ cls0, const float* __restrict__ anc0,
    const float* __restrict__ obj1, const float* __restrict__ reg1,
    const float* __restrict__ cls1, const float* __restrict__ anc1,
    const float* __restrict__ obj2, const float* __restrict__ reg2,
    const float* __restrict__ cls2, const float* __restrict__ anc2)
{
    int a = blockIdx.x * blockDim.x + threadIdx.x;
    if (a >= BATCH * NTOT) return;
    int b = a / NTOT;
    int n = a - b * NTOT;

    const float *obj, *reg, *cls, *anc;
    int local, cnt;
    if (n < N0)        { obj = obj0; reg = reg0; cls = cls0; anc = anc0; local = n;        cnt = N0; }
    else if (n < OFF2) { obj = obj1; reg = reg1; cls = cls1; anc = anc1; local = n - OFF1; cnt = N1; }
    else               { obj = obj2; reg = reg2; cls = cls2; anc = anc2; local = n - OFF2; cnt = N2; }

    size_t base = (size_t)b * cnt + local;

    float o = sigm(__ldg(obj + base));

    // max + argmax over 80 class logits (sigmoid is monotone -> argmax on raw,
    // max sigmoid == sigmoid(max raw); strict '>' gives first-occurrence like jnp.argmax)
    const float4* cp4 = reinterpret_cast<const float4*>(cls + base * 80);
    float best;
    int bi = 0;
    {
        float4 v0 = __ldg(cp4);
        best = v0.x;
        if (v0.y > best) { best = v0.y; bi = 1; }
        if (v0.z > best) { best = v0.z; bi = 2; }
        if (v0.w > best) { best = v0.w; bi = 3; }
    }
#pragma unroll
    for (int j = 1; j < 20; ++j) {
        float4 v = __ldg(cp4 + j);
        if (v.x > best) { best = v.x; bi = 4 * j; }
        if (v.y > best) { best = v.y; bi = 4 * j + 1; }
        if (v.z > best) { best = v.z; bi = 4 * j + 2; }
        if (v.w > best) { best = v.w; bi = 4 * j + 3; }
    }
    float score = sigm(best) * o;

    float4 r = __ldg(reinterpret_cast<const float4*>(reg + base * 4));
    const float* ap = anc + base * 5;
    float ax = __ldg(ap),     ay = __ldg(ap + 1);
    float aw = __ldg(ap + 2), ah = __ldg(ap + 3);
    float st = __ldg(ap + 4);

    // exactly mirror the reference op order; _rn intrinsics block FMA contraction
    float cx = __fmul_rn(__fadd_rn(sigm(r.x), ax), st);
    float cy = __fmul_rn(__fadd_rn(sigm(r.y), ay), st);
    float w  = __fdiv_rn(__fmul_rn(expf(r.z), aw), st);
    float h  = __fdiv_rn(__fmul_rn(expf(r.w), ah), st);
    float x1 = __fsub_rn(cx, __fmul_rn(0.5f, w));
    float y1 = __fsub_rn(cy, __fmul_rn(0.5f, h));
    float x2 = __fadd_rn(w, x1);
    float y2 = __fadd_rn(h, y1);

    // C cast truncates toward zero == jnp astype(int32)
    int xi1 = max((int)x1, 0);
    int yi1 = max((int)y1, 0);
    int xi2 = min((int)x2, IMGMAX);
    int yi2 = min((int)y2, IMGMAX);

    g_score[a] = score;
    g_box[a]   = make_int4(xi1, yi1, xi2, yi2);
    g_cls[a]   = bi;
}

// ---------------- stage 2: exact per-(image,level) top-1000 ----------------
// grid (3, 8): blockIdx.x = level, blockIdx.y = image. 256 threads.
__global__ void topk_kernel()
{
    int level = blockIdx.x, b = blockIdx.y;
    int offs = (level == 0) ? 0  : ((level == 1) ? OFF1 : OFF2);
    int cnt  = (level == 0) ? N0 : ((level == 1) ? N1  : N2);
    const float* sc = g_score + b * NTOT + offs;

    __shared__ unsigned sred[256];
    __shared__ unsigned s_lo, s_hi;
    int tid = threadIdx.x;

    if (tid == 0) { s_lo = 0u; s_hi = 0x3F800000u; }   // scores in (0,1)

    // binary search on float bit-space (positive floats: bits are order-preserving).
    // Find minimal tau with count(bits > tau) < TOPK  ==> tau = bits of k-th largest.
    for (;;) {
        __syncthreads();
        unsigned lo = s_lo, hi = s_hi;
        if (lo >= hi) break;
        unsigned mid = lo + ((hi - lo) >> 1);
        unsigned c = 0;
        for (int i = tid; i < cnt; i += 256)
            c += (__float_as_uint(__ldg(sc + i)) > mid) ? 1u : 0u;
        sred[tid] = c; __syncthreads();
        for (int s = 128; s > 0; s >>= 1) { if (tid < s) sred[tid] += sred[tid + s]; __syncthreads(); }
        if (tid == 0) { if (sred[0] < (unsigned)TOPK) s_hi = mid; else s_lo = mid + 1u; }
    }
    __syncthreads();
    unsigned tau = s_lo;

    // deterministic compaction of strictly-greater entries (thread-strided, scan-based)
    unsigned c = 0;
    for (int i = tid; i < cnt; i += 256)
        c += (__float_as_uint(__ldg(sc + i)) > tau) ? 1u : 0u;
    sred[tid] = c; __syncthreads();
    for (int d = 1; d < 256; d <<= 1) {
        unsigned v = (tid >= d) ? sred[tid - d] : 0u;
        __syncthreads();
        sred[tid] += v;
        __syncthreads();
    }
    unsigned excl = sred[tid] - c;
    unsigned mtot = sred[255];          // # strictly greater (< TOPK by construction)

    unsigned pos = excl;
    for (int i = tid; i < cnt; i += 256) {
        if (__float_as_uint(__ldg(sc + i)) > tau) {
            int g = b * NTOT + offs + i;
            int s = b * NCAND + level * TOPK + (int)pos;
            g_cscore[s] = g_score[g];
            g_cbox[s]   = g_box[g];
            g_ccls[s]   = g_cls[g];
            pos++;
        }
    }

    // fill remaining slots with == tau entries in ascending index order (top_k tie rule)
    int r = TOPK - (int)mtot;
    int last = -1;
    for (int rep = 0; rep < r; ++rep) {
        __syncthreads();
        unsigned lm = 0xFFFFFFFFu;
        for (int i = tid; i < cnt; i += 256) {
            if (i > last && __float_as_uint(__ldg(sc + i)) == tau) { lm = (unsigned)i; break; }
        }
        sred[tid] = lm; __syncthreads();
        for (int s = 128; s > 0; s >>= 1) { if (tid < s) sred[tid] = min(sred[tid], sred[tid + s]); __syncthreads(); }
        unsigned found = sred[0];
        if (tid == 0 && found != 0xFFFFFFFFu) {
            int g = b * NTOT + offs + (int)found;
            int s = b * NCAND + level * TOPK + (int)mtot + rep;
            g_cscore[s] = g_score[g];
            g_cbox[s]   = g_box[g];
            g_ccls[s]   = g_cls[g];
        }
        last = (int)found;
        __syncthreads();
    }
}

// ---------------- stage 3: per-image sort (bitonic, smem) + greedy NMS ----------------
#define SBOX 864   // boxes pre-staged to smem for the sequential NMS loop

__global__ void __launch_bounds__(1024) sortnms_kernel(float* __restrict__ out)
{
    int b = blockIdx.x;
    __shared__ unsigned long long keys[4096];
    __shared__ int4  sbox[SBOX];
    __shared__ float kx1[MAXDET], ky1[MAXDET], kx2[MAXDET], ky2[MAXDET], kar[MAXDET];

    int tid = threadIdx.x;
    const float* cs = g_cscore + b * NCAND;

    // key = score_bits << 32 | (~slot)  -> descending sort == score desc, slot asc on ties
    for (int i = tid; i < 4096; i += 1024) {
        unsigned long long key = 0ull;
        if (i < NCAND)
            key = ((unsigned long long)__float_as_uint(__ldg(cs + i)) << 32)
                | (unsigned long long)(0xFFFFFFFFu - (unsigned)i);
        keys[i] = key;
    }
    __syncthreads();

    // bitonic sort, descending
    for (int k = 2; k <= 4096; k <<= 1) {
        for (int j = k >> 1; j > 0; j >>= 1) {
            for (int i = tid; i < 4096; i += 1024) {
                int ixj = i ^ j;
                if (ixj > i) {
                    bool up = ((i & k) == 0);
                    unsigned long long a = keys[i], c2 = keys[ixj];
                    bool sw = up ? (a < c2) : (a > c2);
                    if (sw) { keys[i] = c2; keys[ixj] = a; }
                }
            }
            __syncthreads();
        }
    }

    // stage the first SBOX sorted boxes into smem (kills serial L2 latency in NMS)
    const int4* cb = g_cbox + b * NCAND;
    for (int i = tid; i < SBOX; i += 1024) {
        int slot = (int)(0xFFFFFFFFu - (unsigned)keys[i]);
        sbox[i] = (slot >= 0 && slot < NCAND) ? __ldg(cb + slot) : make_int4(0, 0, 0, 0);
    }
    __syncthreads();

    // warp 0: greedy class-agnostic NMS (== reference fori_loop + cumsum slotting)
    if (tid < 32) {
        const int* cc = g_ccls + b * NCAND;
        int nkept = 0;
        for (int c = 0; c < NCAND && nkept < MAXDET; ++c) {
            unsigned long long key = keys[c];
            float score = __uint_as_float((unsigned)(key >> 32));
            if (!(score > 0.05f)) break;   // invalid; all subsequent are <= this score
            int slot = (int)(0xFFFFFFFFu - (unsigned)key);
            int4 bx = (c < SBOX) ? sbox[c] : __ldg(cb + slot);
            float x1 = (float)bx.x, y1 = (float)bx.y, x2 = (float)bx.z, y2 = (float)bx.w;
            float area = (x2 - x1) * (y2 - y1);   // exact: integer-valued, < 2^24

            bool sup = false;
            for (int t = tid; t < nkept; t += 32) {
                float xx1 = fmaxf(kx1[t], x1), yy1 = fmaxf(ky1[t], y1);
                float xx2 = fminf(kx2[t], x2), yy2 = fminf(ky2[t], y2);
                float inter = fmaxf(xx2 - xx1, 0.0f) * fmaxf(yy2 - yy1, 0.0f);
                // all terms exactly representable ints; only the divide rounds -> IEEE rn
                float iou = __fdiv_rn(inter, (kar[t] + area) - inter);
                sup |= (iou > 0.5f);
            }
            if (!__any_sync(0xFFFFFFFFu, sup)) {
                if (tid == 0) {
                    kx1[nkept] = x1; ky1[nkept] = y1; kx2[nkept] = x2; ky2[nkept] = y2; kar[nkept] = area;
                    out[b * MAXDET + nkept] = score;
                    out[BATCH * MAXDET + b * MAXDET + nkept] = (float)__ldg(cc + slot);
                    int ob = 2 * BATCH * MAXDET + (b * MAXDET + nkept) * 4;
                    out[ob] = x1; out[ob + 1] = y1; out[ob + 2] = x2; out[ob + 3] = y2;
                }
                nkept++;
                __syncwarp();
            }
        }
        // pad unfilled detection slots with -1
        for (int t = nkept + tid; t < MAXDET; t += 32) {
            out[b * MAXDET + t] = -1.0f;
            out[BATCH * MAXDET + b * MAXDET + t] = -1.0f;
            int ob = 2 * BATCH * MAXDET + (b * MAXDET + t) * 4;
            out[ob] = -1.0f; out[ob + 1] = -1.0f; out[ob + 2] = -1.0f; out[ob + 3] = -1.0f;
        }
    }
}

// ---------------- launcher ----------------
extern "C" void kernel_launch(void* const* d_in, const int* in_sizes, int n_in,
                              void* d_out, int out_size)
{
    (void)out_size;
    // Two plausible metadata orders; disambiguate via element counts.
    // dict order: obj0,reg0,cls0,anc0, obj1,reg1,cls1,anc1, obj2,reg2,cls2,anc2
    static const int dictSizes[12] = {  8664,  34656,   693120,  43320,
                                       34656, 138624,  2772480, 173280,
                                      138624, 554496, 11089920, 693120 };
    // signature order: obj0..2, reg0..2, cls0..2, anc0..2
    static const int sigSizes[12]  = {  8664,  34656, 138624,
                                       34656, 138624, 554496,
                                      693120, 2772480, 11089920,
                                       43320, 173280, 693120 };
    bool isDict = (n_in >= 12), isSig = (n_in >= 12);
    for (int i = 0; i < 12 && i < n_in; i++) {
        if (in_sizes[i] != dictSizes[i]) isDict = false;
        if (in_sizes[i] != sigSizes[i])  isSig  = false;
    }

    // in[] canonical layout: obj0,obj1,obj2, reg0,reg1,reg2, cls0,cls1,cls2, anc0,anc1,anc2
    const float* in[12];
    if (isSig && !isDict) {
        for (int i = 0; i < 12; i++) in[i] = (const float*)d_in[i];
    } else {
        for (int l = 0; l < 3; l++) {
            in[l]     = (const float*)d_in[4 * l + 0];
            in[3 + l] = (const float*)d_in[4 * l + 1];
            in[6 + l] = (const float*)d_in[4 * l + 2];
            in[9 + l] = (const float*)d_in[4 * l + 3];
        }
    }

    decode_kernel<<<(BATCH * NTOT + 255) / 256, 256>>>(
        in[0], in[3], in[6], in[9],
        in[1], in[4], in[7], in[10],
        in[2], in[5], in[8], in[11]);

    dim3 g2(3, BATCH);
    topk_kernel<<<g2, 256>>>();

    sortnms_kernel<<<BATCH, 1024>>>((float*)d_out);
}

// round 2
// speedup vs baseline: 2.1062x; 2.1062x over previous
#include <cuda_runtime.h>
#include <math.h>

// ---------------- problem constants ----------------
#define NTOT   22743
#define N0     1083
#define N1     4332
#define N2     17328
#define OFF1   1083
#define OFF2   5415
#define BATCH  8
#define TOPK   1000
#define NCAND  3000
#define MAXDET 100
#define IMGMAX 607
#define SORTN  4096
#define TS     256        // NMS tile size
#define TW     8          // TS/32

// ---------------- device scratch ----------------
__device__ float g_score[BATCH * NTOT];
__device__ int4  g_box[BATCH * NTOT];
__device__ int   g_cls[BATCH * NTOT];

__device__ float g_cscore[BATCH * NCAND];
__device__ int4  g_cbox[BATCH * NCAND];
__device__ int   g_ccls[BATCH * NCAND];

__device__ unsigned long long g_skeys[BATCH * SORTN];

__device__ __forceinline__ float sigm(float x) { return 1.0f / (1.0f + expf(-x)); }

// ---------------- stage 1: decode (2 threads per anchor) ----------------
__global__ void decode_kernel(
    const float* __restrict__ obj0, const float* __restrict__ reg0,
    const float* __restrict__ cls0, const float* __restrict__ anc0,
    const float* __restrict__ obj1, const float* __restrict__ reg1,
    const float* __restrict__ cls1, const float* __restrict__ anc1,
    const float* __restrict__ obj2, const float* __restrict__ reg2,
    const float* __restrict__ cls2, const float* __restrict__ anc2)
{
    int t = blockIdx.x * blockDim.x + threadIdx.x;
    int a = t >> 1;
    int sub = t & 1;
    if (a >= BATCH * NTOT) a = BATCH * NTOT - 1;   // clamp: duplicates write same data
    int b = a / NTOT;
    int n = a - b * NTOT;

    const float *obj, *reg, *cls, *anc;
    int local, cnt;
    if (n < N0)        { obj = obj0; reg = reg0; cls = cls0; anc = anc0; local = n;        cnt = N0; }
    else if (n < OFF2) { obj = obj1; reg = reg1; cls = cls1; anc = anc1; local = n - OFF1; cnt = N1; }
    else               { obj = obj2; reg = reg2; cls = cls2; anc = anc2; local = n - OFF2; cnt = N2; }

    size_t base = (size_t)b * cnt + local;

    // each of the 2 threads reduces 40 classes (10 float4)
    const float4* cp4 = reinterpret_cast<const float4*>(cls + base * 80) + sub * 10;
    float best;
    int bi = 0;
    {
        float4 v = __ldg(cp4);
        best = v.x;
        if (v.y > best) { best = v.y; bi = 1; }
        if (v.z > best) { best = v.z; bi = 2; }
        if (v.w > best) { best = v.w; bi = 3; }
    }
#pragma unroll
    for (int j = 1; j < 10; ++j) {
        float4 v = __ldg(cp4 + j);
        if (v.x > best) { best = v.x; bi = 4 * j; }
        if (v.y > best) { best = v.y; bi = 4 * j + 1; }
        if (v.z > best) { best = v.z; bi = 4 * j + 2; }
        if (v.w > best) { best = v.w; bi = 4 * j + 3; }
    }
    bi += sub * 40;

    float pb  = __shfl_xor_sync(0xffffffffu, best, 1);
    int   pbi = __shfl_xor_sync(0xffffffffu, bi, 1);

    if (sub == 0) {
        // even lane holds classes 0..39 (lower indices): strict '>' keeps first occurrence
        if (pb > best) { best = pb; bi = pbi; }

        float o = sigm(__ldg(obj + base));
        float score = sigm(best) * o;

        float4 r = __ldg(reinterpret_cast<const float4*>(reg + base * 4));
        const float* ap = anc + base * 5;
        float ax = __ldg(ap),     ay = __ldg(ap + 1);
        float aw = __ldg(ap + 2), ah = __ldg(ap + 3);
        float st = __ldg(ap + 4);

        float cx = __fmul_rn(__fadd_rn(sigm(r.x), ax), st);
        float cy = __fmul_rn(__fadd_rn(sigm(r.y), ay), st);
        float w  = __fdiv_rn(__fmul_rn(expf(r.z), aw), st);
        float h  = __fdiv_rn(__fmul_rn(expf(r.w), ah), st);
        float x1 = __fsub_rn(cx, __fmul_rn(0.5f, w));
        float y1 = __fsub_rn(cy, __fmul_rn(0.5f, h));
        float x2 = __fadd_rn(w, x1);
        float y2 = __fadd_rn(h, y1);

        int xi1 = max((int)x1, 0);
        int yi1 = max((int)y1, 0);
        int xi2 = min((int)x2, IMGMAX);
        int yi2 = min((int)y2, IMGMAX);

        g_score[a] = score;
        g_box[a]   = make_int4(xi1, yi1, xi2, yi2);
        g_cls[a]   = bi;
    }
}

// ---------------- stage 2: register-cached exact top-1000 ----------------
#define TKT 512
#define PER 34   // ceil(17328/512)

__global__ void __launch_bounds__(TKT) topk_kernel()
{
    int level = blockIdx.x, b = blockIdx.y;
    int offs = (level == 0) ? 0  : ((level == 1) ? OFF1 : OFF2);
    int cnt  = (level == 0) ? N0 : ((level == 1) ? N1  : N2);
    const unsigned* sc = reinterpret_cast<const unsigned*>(g_score + b * NTOT + offs);

    int tid = threadIdx.x;
    int lane = tid & 31, warp = tid >> 5;

    unsigned v[PER];
#pragma unroll
    for (int k = 0; k < PER; ++k) {
        int i = tid + (k << 9);
        v[k] = (i < cnt) ? __ldg(sc + i) : 0u;
    }

    __shared__ unsigned wred[16];
    __shared__ unsigned sb[2];
    __shared__ int s_found;
    if (tid == 0) { sb[0] = 0u; sb[1] = 0x3F800000u; }
    __syncthreads();

    unsigned lo = 0u, hi = 0x3F800000u;
    while (lo < hi) {
        unsigned mid = lo + ((hi - lo) >> 1);
        unsigned c = 0;
#pragma unroll
        for (int k = 0; k < PER; ++k) c += (v[k] > mid) ? 1u : 0u;
#pragma unroll
        for (int o = 16; o; o >>= 1) c += __shfl_down_sync(0xffffffffu, c, o);
        if (lane == 0) wred[warp] = c;
        __syncthreads();
        if (tid < 32) {
            unsigned s = (tid < 16) ? wred[tid] : 0u;
#pragma unroll
            for (int o = 8; o; o >>= 1) s += __shfl_down_sync(0xffffffffu, s, o);
            if (tid == 0) { if (s < (unsigned)TOPK) sb[1] = mid; else sb[0] = mid + 1u; }
        }
        __syncthreads();
        lo = sb[0]; hi = sb[1];
        __syncthreads();           // protect wred reuse next iteration
    }
    unsigned tau = lo;

    // exclusive scan of per-thread strictly-greater counts
    unsigned c = 0;
#pragma unroll
    for (int k = 0; k < PER; ++k) c += (v[k] > tau) ? 1u : 0u;
    unsigned ws = c;
#pragma unroll
    for (int o = 1; o < 32; o <<= 1) {
        unsigned nb = __shfl_up_sync(0xffffffffu, ws, o);
        if (lane >= o) ws += nb;
    }
    if (lane == 31) wred[warp] = ws;
    __syncthreads();
    if (tid < 32) {
        unsigned s = (tid < 16) ? wred[tid] : 0u;
#pragma unroll
        for (int o = 1; o < 16; o <<= 1) {
            unsigned nb = __shfl_up_sync(0xffffffffu, s, o);
            if (lane >= o) s += nb;
        }
        if (tid < 16) wred[tid] = s;
    }
    __syncthreads();
    unsigned excl = ws - c + (warp ? wred[warp - 1] : 0u);
    unsigned mtot = wred[15];

    unsigned pos = excl;
#pragma unroll
    for (int k = 0; k < PER; ++k) {
        int i = tid + (k << 9);
        if (i < cnt && v[k] > tau) {
            int g = b * NTOT + offs + i;
            int s = b * NCAND + level * TOPK + (int)pos;
            g_cscore[s] = __uint_as_float(v[k]);
            g_cbox[s]   = g_box[g];
            g_ccls[s]   = g_cls[g];
            pos++;
        }
    }
    __syncthreads();

    // fill remaining slots with == tau entries, ascending index (top_k tie rule)
    int r = TOPK - (int)mtot;
    int last = -1;
    for (int rep = 0; rep < r; ++rep) {
        unsigned lm = 0xFFFFFFFFu;
#pragma unroll
        for (int k = 0; k < PER; ++k) {
            int i = tid + (k << 9);
            if (i < cnt && i > last && v[k] == tau) lm = min(lm, (unsigned)i);
        }
#pragma unroll
        for (int o = 16; o; o >>= 1) lm = min(lm, __shfl_down_sync(0xffffffffu, lm, o));
        if (lane == 0) wred[warp] = lm;
        __syncthreads();
        if (tid < 32) {
            unsigned s = (tid < 16) ? wred[tid] : 0xFFFFFFFFu;
#pragma unroll
            for (int o = 8; o; o >>= 1) s = min(s, __shfl_down_sync(0xffffffffu, s, o));
            if (tid == 0) s_found = (int)s;
        }
        __syncthreads();
        int found = s_found;
        if (tid == 0 && found >= 0 && found < cnt) {
            int g = b * NTOT + offs + found;
            int s = b * NCAND + level * TOPK + (int)mtot + rep;
            g_cscore[s] = g_score[g];
            g_cbox[s]   = g_box[g];
            g_ccls[s]   = g_cls[g];
        }
        last = found;
        __syncthreads();
    }
}

// ---------------- stage 3a: bitonic sort, 4 elems/thread ----------------
__device__ __forceinline__ unsigned long long u64max(unsigned long long a, unsigned long long b) { return a > b ? a : b; }
__device__ __forceinline__ unsigned long long u64min(unsigned long long a, unsigned long long b) { return a < b ? a : b; }
__device__ __forceinline__ void cswap(unsigned long long& a, unsigned long long& b, bool desc)
{
    // desc: larger first
    if (desc ? (a < b) : (a > b)) { unsigned long long t = a; a = b; b = t; }
}

__global__ void __launch_bounds__(1024) sort_kernel()
{
    int b = blockIdx.x;
    int t = threadIdx.x;
    int i0 = t << 2;
    __shared__ unsigned long long sk[SORTN];

    const float* cs = g_cscore + b * NCAND;
    unsigned long long r[4];
#pragma unroll
    for (int s = 0; s < 4; ++s) {
        int i = i0 + s;
        r[s] = (i < NCAND)
             ? (((unsigned long long)__float_as_uint(__ldg(cs + i)) << 32)
                | (unsigned long long)(0xFFFFFFFFu - (unsigned)i))
             : 0ull;
    }

    for (int k = 2; k <= SORTN; k <<= 1) {
        for (int j = k >> 1; j > 0; j >>= 1) {
            if (j >= 128) {
                sk[i0] = r[0]; sk[i0 + 1] = r[1]; sk[i0 + 2] = r[2]; sk[i0 + 3] = r[3];
                __syncthreads();
                int pb = i0 ^ j;
                bool takeMax = (((i0 & k) == 0) != ((i0 & j) != 0));
#pragma unroll
                for (int s = 0; s < 4; ++s) {
                    unsigned long long p = sk[pb + s];
                    r[s] = takeMax ? u64max(r[s], p) : u64min(r[s], p);
                }
                __syncthreads();
            } else if (j >= 4) {
                int lx = j >> 2;
                bool takeMax = (((i0 & k) == 0) != ((i0 & j) != 0));
#pragma unroll
                for (int s = 0; s < 4; ++s) {
                    unsigned long long p = __shfl_xor_sync(0xffffffffu, r[s], lx);
                    r[s] = takeMax ? u64max(r[s], p) : u64min(r[s], p);
                }
            } else if (j == 2) {
                cswap(r[0], r[2], ((i0    ) & k) == 0);
                cswap(r[1], r[3], ((i0 + 1) & k) == 0);
            } else {
                cswap(r[0], r[1], ((i0    ) & k) == 0);
                cswap(r[2], r[3], ((i0 + 2) & k) == 0);
            }
        }
    }

    unsigned long long* out = g_skeys + b * SORTN;
#pragma unroll
    for (int s = 0; s < 4; ++s) out[i0 + s] = r[s];
}

// ---------------- stage 3b: tiled bitmask NMS ----------------
// Exact int equivalence: iou > 0.5  <=>  inter > 0 && 3*inter > area_i + area_j
// (all quantities exact integers < 2^21; the reference's float divide cannot
//  cross the 0.5 boundary: min gap 2^-21 > max rounding error 2^-25)
__global__ void __launch_bounds__(1024) nms_kernel(float* __restrict__ out)
{
    int b = blockIdx.x;
    int tid = threadIdx.x;

    __shared__ int tx1[TS], ty1[TS], tx2[TS], ty2[TS], tar[TS], tcl[TS];
    __shared__ float tsc[TS];
    __shared__ unsigned M[TS][TW];
    __shared__ unsigned supv[TW];
    __shared__ int kx1[MAXDET], ky1[MAXDET], kx2[MAXDET], ky2[MAXDET], kar[MAXDET];
    __shared__ int s_state[2];     // kept, done

    if (tid == 0) { s_state[0] = 0; s_state[1] = 0; }
    __syncthreads();

    const unsigned long long* keys = g_skeys + b * SORTN;
    const int4* cb = g_cbox + b * NCAND;
    const int*  cc = g_ccls + b * NCAND;

    for (int tile = 0; tile < NCAND; tile += TS) {
        // ---- load tile ----
        if (tid < TS) {
            unsigned long long key = keys[tile + tid];
            float sc = __uint_as_float((unsigned)(key >> 32));
            unsigned slot = 0xFFFFFFFFu - (unsigned)key;
            tsc[tid] = sc;
            int4 bx = make_int4(0, 0, 0, 0);
            int cl = 0;
            if (slot < (unsigned)NCAND) { bx = __ldg(cb + slot); cl = __ldg(cc + slot); }
            tx1[tid] = bx.x; ty1[tid] = bx.y; tx2[tid] = bx.z; ty2[tid] = bx.w;
            tar[tid] = (bx.z - bx.x) * (bx.w - bx.y);
            tcl[tid] = cl;
        }
        __syncthreads();

        // ---- suppression vs already-kept boxes ----
        int kept0 = s_state[0];
        if (tid < TS) {
            bool sup = false;
            int x1 = tx1[tid], y1 = ty1[tid], x2 = tx2[tid], y2 = ty2[tid], ar = tar[tid];
            for (int k2 = 0; k2 < kept0; ++k2) {
                int iw = min(x2, kx2[k2]) - max(x1, kx1[k2]);
                int ih = min(y2, ky2[k2]) - max(y1, ky1[k2]);
                if (iw > 0 && ih > 0) {
                    int inter = iw * ih;
                    if (3 * inter > ar + kar[k2]) sup = true;
                }
            }
            unsigned bal = __ballot_sync(0xffffffffu, sup);
            if ((tid & 31) == 0) supv[tid >> 5] = bal;
        }

        // ---- within-tile suppression matrix (warp lanes share w -> broadcast LDS) ----
        for (int task = tid; task < TS * TW; task += 1024) {
            int w = task >> 8;           // word index: uniform across warp lanes
            int i = task & (TS - 1);     // candidate row
            unsigned bits = 0u;
            int jbase = w << 5;
            if (jbase + 31 > i) {
                int x1 = tx1[i], y1 = ty1[i], x2 = tx2[i], y2 = ty2[i], ar = tar[i];
#pragma unroll 8
                for (int jj = 0; jj < 32; ++jj) {
                    int j = jbase + jj;
                    if (j > i) {
                        int iw = min(x2, tx2[j]) - max(x1, tx1[j]);
                        int ih = min(y2, ty2[j]) - max(y1, ty1[j]);
                        if (iw > 0 && ih > 0) {
                            int inter = iw * ih;
                            if (3 * inter > ar + tar[j]) bits |= (1u << jj);
                        }
                    }
                }
            }
            M[i][w] = bits;
        }
        __syncthreads();

        // ---- warp-0 bit-DP (greedy, exact order) ----
        if (tid < 32) {
            int kept = s_state[0];
            int done = 0;
            for (int g = 0; g < TW && !done; ++g) {
                int base = g << 5;
                float sc = tsc[base + tid];
                unsigned validm = __ballot_sync(0xffffffffu, sc > 0.05f);
                unsigned alive = validm & ~supv[g];
                while (alive) {
                    int bpos = __ffs(alive) - 1;
                    int i = base + bpos;
                    alive &= ~(1u << bpos);
                    if (tid == 0) {
                        kx1[kept] = tx1[i]; ky1[kept] = ty1[i];
                        kx2[kept] = tx2[i]; ky2[kept] = ty2[i];
                        kar[kept] = tar[i];
                        out[b * MAXDET + kept] = tsc[i];
                        out[BATCH * MAXDET + b * MAXDET + kept] = (float)tcl[i];
                        int ob = 2 * BATCH * MAXDET + (b * MAXDET + kept) * 4;
                        out[ob]     = (float)tx1[i];
                        out[ob + 1] = (float)ty1[i];
                        out[ob + 2] = (float)tx2[i];
                        out[ob + 3] = (float)ty2[i];
                    }
                    kept++;
                    if (kept == MAXDET) { done = 1; break; }
                    alive &= ~M[i][g];
                    if (tid < TW) supv[tid] |= M[i][tid];
                    __syncwarp();
                }
                if (validm != 0xFFFFFFFFu) done = 1;
            }
            if (tid == 0) { s_state[0] = kept; s_state[1] = done; }
        }
        __syncthreads();
        if (s_state[1]) break;
        __syncthreads();
    }

    // ---- pad unfilled slots ----
    int kept = s_state[0];
    for (int i = kept + tid; i < MAXDET; i += 1024) {
        out[b * MAXDET + i] = -1.0f;
        out[BATCH * MAXDET + b * MAXDET + i] = -1.0f;
        int ob = 2 * BATCH * MAXDET + (b * MAXDET + i) * 4;
        out[ob] = -1.0f; out[ob + 1] = -1.0f; out[ob + 2] = -1.0f; out[ob + 3] = -1.0f;
    }
}

// ---------------- launcher ----------------
extern "C" void kernel_launch(void* const* d_in, const int* in_sizes, int n_in,
                              void* d_out, int out_size)
{
    (void)out_size;
    static const int dictSizes[12] = {  8664,  34656,   693120,  43320,
                                       34656, 138624,  2772480, 173280,
                                      138624, 554496, 11089920, 693120 };
    static const int sigSizes[12]  = {  8664,  34656, 138624,
                                       34656, 138624, 554496,
                                      693120, 2772480, 11089920,
                                       43320, 173280, 693120 };
    bool isDict = (n_in >= 12), isSig = (n_in >= 12);
    for (int i = 0; i < 12 && i < n_in; i++) {
        if (in_sizes[i] != dictSizes[i]) isDict = false;
        if (in_sizes[i] != sigSizes[i])  isSig  = false;
    }

    const float* in[12];
    if (isSig && !isDict) {
        for (int i = 0; i < 12; i++) in[i] = (const float*)d_in[i];
    } else {
        for (int l = 0; l < 3; l++) {
            in[l]     = (const float*)d_in[4 * l + 0];
            in[3 + l] = (const float*)d_in[4 * l + 1];
            in[6 + l] = (const float*)d_in[4 * l + 2];
            in[9 + l] = (const float*)d_in[4 * l + 3];
        }
    }

    int nthreads = BATCH * NTOT * 2;
    decode_kernel<<<(nthreads + 255) / 256, 256>>>(
        in[0], in[3], in[6], in[9],
        in[1], in[4], in[7], in[10],
        in[2], in[5], in[8], in[11]);

    dim3 g2(3, BATCH);
    topk_kernel<<<g2, TKT>>>();

    sort_kernel<<<BATCH, 1024>>>();

    nms_kernel<<<BATCH, 1024>>>((float*)d_out);
}